// round 1
// baseline (speedup 1.0000x reference)
#include <cuda_runtime.h>
#include <math.h>

// ---------------------------------------------------------------------------
// Interpolation: per-column (C=16) mean of non-NaN entries over T=2M, then
// fill NaNs with that mean. Shape [1, 2,000,000, 16] f32, contiguous, so
// element e has column (e & 15); a float4 v covers columns 4*(v&3)..4*(v&3)+3.
// ---------------------------------------------------------------------------

#define COLS 16
#define NBLOCKS (148 * 8)   // one full resident wave: 1184 blocks * 8 warps = 64 warps/SM
#define NTHREADS 256

__device__ float g_sum[COLS];
__device__ float g_cnt[COLS];
__device__ float g_mean[COLS];

__global__ void interp_zero_kernel() {
    int i = threadIdx.x;
    if (i < COLS) { g_sum[i] = 0.0f; g_cnt[i] = 0.0f; }
}

__global__ void __launch_bounds__(NTHREADS) interp_reduce_kernel(
    const float4* __restrict__ in, int n4)
{
    __shared__ float s_sum[COLS];
    __shared__ float s_cnt[COLS];
    int t = threadIdx.x;
    if (t < COLS) { s_sum[t] = 0.0f; s_cnt[t] = 0.0f; }
    __syncthreads();

    int idx    = blockIdx.x * NTHREADS + t;
    int stride = NBLOCKS * NTHREADS;          // multiple of 4 -> (v & 3) constant per thread
    int g      = idx & 3;                      // column group: cols 4g..4g+3

    float s0 = 0.f, s1 = 0.f, s2 = 0.f, s3 = 0.f;
    float c0 = 0.f, c1 = 0.f, c2 = 0.f, c3 = 0.f;

    for (int v = idx; v < n4; v += stride) {
        float4 x = in[v];
        bool v0 = (x.x == x.x), v1 = (x.y == x.y), v2 = (x.z == x.z), v3 = (x.w == x.w);
        s0 += v0 ? x.x : 0.0f;  c0 += v0 ? 1.0f : 0.0f;
        s1 += v1 ? x.y : 0.0f;  c1 += v1 ? 1.0f : 0.0f;
        s2 += v2 ? x.z : 0.0f;  c2 += v2 ? 1.0f : 0.0f;
        s3 += v3 ? x.w : 0.0f;  c3 += v3 ? 1.0f : 0.0f;
    }

    atomicAdd(&s_sum[4 * g + 0], s0);  atomicAdd(&s_cnt[4 * g + 0], c0);
    atomicAdd(&s_sum[4 * g + 1], s1);  atomicAdd(&s_cnt[4 * g + 1], c1);
    atomicAdd(&s_sum[4 * g + 2], s2);  atomicAdd(&s_cnt[4 * g + 2], c2);
    atomicAdd(&s_sum[4 * g + 3], s3);  atomicAdd(&s_cnt[4 * g + 3], c3);
    __syncthreads();

    if (t < COLS) {
        atomicAdd(&g_sum[t], s_sum[t]);
        atomicAdd(&g_cnt[t], s_cnt[t]);
    }
}

__global__ void interp_finalize_kernel() {
    int i = threadIdx.x;
    if (i < COLS) g_mean[i] = g_sum[i] / fmaxf(g_cnt[i], 1.0f);
}

__global__ void __launch_bounds__(NTHREADS) interp_fill_kernel(
    const float4* __restrict__ in, float4* __restrict__ out, int n4)
{
    int t      = threadIdx.x;
    int idx    = blockIdx.x * NTHREADS + t;
    int stride = NBLOCKS * NTHREADS;
    int g      = idx & 3;

    float m0 = g_mean[4 * g + 0];
    float m1 = g_mean[4 * g + 1];
    float m2 = g_mean[4 * g + 2];
    float m3 = g_mean[4 * g + 3];

    // Reverse grid-stride: start from the tail of the tensor, which is the
    // part of the input still resident in L2 after the reduce pass (128 MB
    // data vs ~126 MB L2 — forward order would cyclically thrash).
    if (idx < n4) {
        int v = idx + ((n4 - 1 - idx) / stride) * stride;   // largest v ≡ idx (mod stride)
        for (; v >= 0; v -= stride) {
            float4 x = __ldcs(&in[v]);   // evict-first: don't re-pollute after use
            float4 o;
            o.x = (x.x == x.x) ? x.x : m0;
            o.y = (x.y == x.y) ? x.y : m1;
            o.z = (x.z == x.z) ? x.z : m2;
            o.w = (x.w == x.w) ? x.w : m3;
            __stcs(&out[v], o);          // streaming store: don't evict cached input
        }
    }
}

extern "C" void kernel_launch(void* const* d_in, const int* in_sizes, int n_in,
                              void* d_out, int out_size)
{
    const float4* in  = (const float4*)d_in[0];
    float4*       out = (float4*)d_out;
    int n4 = in_sizes[0] / 4;   // 32,000,000 / 4 = 8,000,000 (exact)

    interp_zero_kernel<<<1, 32>>>();
    interp_reduce_kernel<<<NBLOCKS, NTHREADS>>>(in, n4);
    interp_finalize_kernel<<<1, 32>>>();
    interp_fill_kernel<<<NBLOCKS, NTHREADS>>>(in, out, n4);
}